// round 10
// baseline (speedup 1.0000x reference)
#include <cuda_runtime.h>
#include <cstdint>

// ---------------------------------------------------------------------------
// GCN (3-layer, sum-aggregate) on GB300.
// R10: fuse aggregation(layer k) + GEMM(layer k+1) into one kernel: each
// block gathers its 128 nodes' neighborhoods (L2-bound) straight into the
// transposed+swizzled smem tile, then runs the FFMA2 GEMM phase from smem.
// Hides GEMM2/3 FMA time under gather L2 time; kills the h global roundtrip.
// Structure: [G1 || CSR-build] -> fused(A1+G2) -> fused(A2+G3) -> A3.
// ---------------------------------------------------------------------------

#define MAX_N 100000
#define MAX_E 1600000

__device__ int   g_deg[MAX_N];
__device__ int   g_off[MAX_N + 1];
__device__ int   g_cur[MAX_N];
__device__ int   g_csr[MAX_E];
__device__ int   g_bsums[256];
__device__ float g_hw[(size_t)MAX_N * 64];
__device__ float g_h [(size_t)MAX_N * 64];

// packed fp32 helpers (Blackwell f32x2 pipe)
#define FMA_F32X2(d, a, b, c) \
    asm("fma.rn.f32x2 %0, %1, %2, %3;" : "=l"(d) : "l"(a), "l"(b), "l"(c))
#define PACK2(out, lo, hi) \
    asm("mov.b64 %0, {%1, %2};" : "=l"(out) : "r"(lo), "r"(hi))
#define UNPACK2(lo, hi, in) \
    asm("mov.b64 {%0, %1}, %2;" : "=r"(lo), "=r"(hi) : "l"(in))

// ---------------- CSR build ----------------

__global__ void zero_deg(int n) {
    int i = blockIdx.x * blockDim.x + threadIdx.x;
    if (i < n) g_deg[i] = 0;
}

__global__ void hist_kernel(const int* __restrict__ dst, int e) {
    int i = blockIdx.x * blockDim.x + threadIdx.x;
    if (i < e) atomicAdd(&g_deg[dst[i]], 1);
}

__global__ void __launch_bounds__(1024) scan_block(int n_total) {
    __shared__ int wsum[32];
    int gid  = blockIdx.x * 1024 + threadIdx.x;
    int lane = threadIdx.x & 31;
    int wid  = threadIdx.x >> 5;
    int v = (gid < n_total - 1) ? g_deg[gid] : 0;

    int inc = v;
    #pragma unroll
    for (int d = 1; d < 32; d <<= 1) {
        int t = __shfl_up_sync(0xffffffffu, inc, d);
        if (lane >= d) inc += t;
    }
    if (lane == 31) wsum[wid] = inc;
    __syncthreads();
    if (wid == 0) {
        int s = wsum[lane];
        #pragma unroll
        for (int d = 1; d < 32; d <<= 1) {
            int t = __shfl_up_sync(0xffffffffu, s, d);
            if (lane >= d) s += t;
        }
        wsum[lane] = s;
    }
    __syncthreads();
    int add = wid ? wsum[wid - 1] : 0;
    if (gid < n_total) g_off[gid] = inc - v + add;
    if (threadIdx.x == 1023) g_bsums[blockIdx.x] = inc + add;
}

__global__ void scan_sums(int nb) {
    __shared__ int ws[4];
    const int t    = threadIdx.x;
    const int lane = t & 31;
    const int w    = t >> 5;
    int v = (t < nb) ? g_bsums[t] : 0;
    int inc = v;
    #pragma unroll
    for (int d = 1; d < 32; d <<= 1) {
        int s = __shfl_up_sync(0xffffffffu, inc, d);
        if (lane >= d) inc += s;
    }
    if (lane == 31) ws[w] = inc;
    __syncthreads();
    int add = 0;
    #pragma unroll
    for (int i = 0; i < 4; i++) add += (i < w) ? ws[i] : 0;
    if (t < nb) g_bsums[t] = inc - v + add;
}

__global__ void __launch_bounds__(1024) scan_add(int n_total) {
    int gid = blockIdx.x * 1024 + threadIdx.x;
    if (gid < n_total) {
        int v = g_off[gid] + g_bsums[blockIdx.x];
        g_off[gid] = v;
        if (gid < n_total - 1) g_cur[gid] = v;
    }
}

__global__ void fill_csr(const int* __restrict__ src, const int* __restrict__ dst, int e) {
    int i = blockIdx.x * blockDim.x + threadIdx.x;
    if (i < e) {
        int p = atomicAdd(&g_cur[dst[i]], 1);
        g_csr[p] = src[i];
    }
}

// ---------------- standalone GEMM (layer 1): Y[n,64] = X[n,K] @ W[K,64] ----
// FFMA2 path, transposed + XOR-swizzled X tile (proven in R9).

template <int K>
__global__ void __launch_bounds__(256) gemm64(const float* __restrict__ X,
                                              const float* __restrict__ W,
                                              float* __restrict__ Y, int n) {
    extern __shared__ float smem[];
    float* xs = smem;                 // [K][128] swizzled, transposed
    float* ws = smem + K * 128;       // [K][64]
    const int t    = threadIdx.x;
    const int base = blockIdx.x * 128;

    for (int i = t; i < K * 16; i += 256)
        ((float4*)ws)[i] = ((const float4*)W)[i];

    for (int i = t; i < 128 * (K / 4); i += 256) {
        int r  = i / (K / 4);
        int c4 = i % (K / 4);
        int node = base + r;
        float4 v = make_float4(0.f, 0.f, 0.f, 0.f);
        if (node < n) v = ((const float4*)(X + (size_t)node * K))[c4];
        int s  = (c4 & 15) << 1;
        int rs = r ^ s;
        xs[(c4 * 4 + 0) * 128 + rs] = v.x;
        xs[(c4 * 4 + 1) * 128 + rs] = v.y;
        xs[(c4 * 4 + 2) * 128 + rs] = v.z;
        xs[(c4 * 4 + 3) * 128 + rs] = v.w;
    }
    __syncthreads();

    const int tx = t & 15;
    const int ty = t >> 4;
    const int c0 = tx * 4;

    unsigned long long acc[4][4];
    #pragma unroll
    for (int j = 0; j < 4; j++)
        #pragma unroll
        for (int c = 0; c < 4; c++) acc[j][c] = 0ULL;

    for (int k4 = 0; k4 < K; k4 += 4) {
        const int s = ((k4 >> 2) & 15) << 1;
        int r0 = (ty * 8 + 0) ^ s;
        int r1 = (ty * 8 + 2) ^ s;
        int r2 = (ty * 8 + 4) ^ s;
        int r3 = (ty * 8 + 6) ^ s;
        #pragma unroll
        for (int kk = 0; kk < 4; kk++) {
            const int k = k4 + kk;
            float4 w4 = *(const float4*)(ws + k * 64 + c0);
            unsigned long long wd0, wd1, wd2, wd3;
            PACK2(wd0, __float_as_uint(w4.x), __float_as_uint(w4.x));
            PACK2(wd1, __float_as_uint(w4.y), __float_as_uint(w4.y));
            PACK2(wd2, __float_as_uint(w4.z), __float_as_uint(w4.z));
            PACK2(wd3, __float_as_uint(w4.w), __float_as_uint(w4.w));
            const float* xr = xs + k * 128;
            unsigned long long x0 = *(const unsigned long long*)(xr + r0);
            unsigned long long x1 = *(const unsigned long long*)(xr + r1);
            unsigned long long x2 = *(const unsigned long long*)(xr + r2);
            unsigned long long x3 = *(const unsigned long long*)(xr + r3);
            FMA_F32X2(acc[0][0], x0, wd0, acc[0][0]);
            FMA_F32X2(acc[0][1], x0, wd1, acc[0][1]);
            FMA_F32X2(acc[0][2], x0, wd2, acc[0][2]);
            FMA_F32X2(acc[0][3], x0, wd3, acc[0][3]);
            FMA_F32X2(acc[1][0], x1, wd0, acc[1][0]);
            FMA_F32X2(acc[1][1], x1, wd1, acc[1][1]);
            FMA_F32X2(acc[1][2], x1, wd2, acc[1][2]);
            FMA_F32X2(acc[1][3], x1, wd3, acc[1][3]);
            FMA_F32X2(acc[2][0], x2, wd0, acc[2][0]);
            FMA_F32X2(acc[2][1], x2, wd1, acc[2][1]);
            FMA_F32X2(acc[2][2], x2, wd2, acc[2][2]);
            FMA_F32X2(acc[2][3], x2, wd3, acc[2][3]);
            FMA_F32X2(acc[3][0], x3, wd0, acc[3][0]);
            FMA_F32X2(acc[3][1], x3, wd1, acc[3][1]);
            FMA_F32X2(acc[3][2], x3, wd2, acc[3][2]);
            FMA_F32X2(acc[3][3], x3, wd3, acc[3][3]);
        }
    }

    #pragma unroll
    for (int j = 0; j < 4; j++) {
        unsigned int lo0, hi0, lo1, hi1, lo2, hi2, lo3, hi3;
        UNPACK2(lo0, hi0, acc[j][0]);
        UNPACK2(lo1, hi1, acc[j][1]);
        UNPACK2(lo2, hi2, acc[j][2]);
        UNPACK2(lo3, hi3, acc[j][3]);
        int n0 = base + ty * 8 + 2 * j;
        if (n0 < n) {
            *(float4*)(Y + (size_t)n0 * 64 + c0) =
                make_float4(__uint_as_float(lo0), __uint_as_float(lo1),
                            __uint_as_float(lo2), __uint_as_float(lo3));
        }
        if (n0 + 1 < n) {
            *(float4*)(Y + (size_t)(n0 + 1) * 64 + c0) =
                make_float4(__uint_as_float(hi0), __uint_as_float(hi1),
                            __uint_as_float(hi2), __uint_as_float(hi3));
        }
    }
}

// ---------------- fused agg(layer k) + GEMM(layer k+1) ----------------
// Phase 1: each warp aggregates 16 of the block's 128 nodes from hw_in
// (CSR gather, half-warp scheme), relu(agg+bias), and scatters the result
// DIRECTLY into the transposed+swizzled xs tile (16 lanes x 4 STS.32,
// bank-conflict-free since s(k)=2q is constant per lane's 4 k-rows).
// Phase 2: FFMA2 GEMM xs @ W -> hw_out (identical to gemm64<64> mainloop).

__global__ void __launch_bounds__(256) fused_agg_gemm(
        const float* __restrict__ hw_in, const float* __restrict__ bias,
        const float* __restrict__ W, float* __restrict__ hw_out, int n) {
    extern __shared__ float smem[];
    float* xs = smem;                 // [64][128] swizzled, transposed
    float* ws = smem + 64 * 128;      // [64][64]
    const int t    = threadIdx.x;
    const int base = blockIdx.x * 128;
    const int wid  = t >> 5;
    const int lane = t & 31;
    const int half = lane >> 4;
    const int q    = lane & 15;

    for (int i = t; i < 64 * 16; i += 256)
        ((float4*)ws)[i] = ((const float4*)W)[i];

    const float4 bq = ((const float4*)bias)[q];

    #pragma unroll 1
    for (int i = 0; i < 16; i++) {
        const int nl   = wid * 16 + i;
        const int node = base + nl;

        float4 a0 = make_float4(0.f, 0.f, 0.f, 0.f);
        float4 a1 = make_float4(0.f, 0.f, 0.f, 0.f);

        if (node < n) {   // warp-uniform branch
            const int beg = g_off[node];
            const int end = g_off[node + 1];
            int e = beg;
            for (; e + 3 < end; e += 4) {
                int s0 = g_csr[e + half];
                int s1 = g_csr[e + 2 + half];
                float4 v0 = ((const float4*)(hw_in + (size_t)s0 * 64))[q];
                float4 v1 = ((const float4*)(hw_in + (size_t)s1 * 64))[q];
                a0.x += v0.x; a0.y += v0.y; a0.z += v0.z; a0.w += v0.w;
                a1.x += v1.x; a1.y += v1.y; a1.z += v1.z; a1.w += v1.w;
            }
            for (; e + 1 < end; e += 2) {
                int s0 = g_csr[e + half];
                float4 v0 = ((const float4*)(hw_in + (size_t)s0 * 64))[q];
                a0.x += v0.x; a0.y += v0.y; a0.z += v0.z; a0.w += v0.w;
            }
            if (e < end && half == 0) {
                int s0 = g_csr[e];
                float4 v0 = ((const float4*)(hw_in + (size_t)s0 * 64))[q];
                a0.x += v0.x; a0.y += v0.y; a0.z += v0.z; a0.w += v0.w;
            }
            a0.x += a1.x; a0.y += a1.y; a0.z += a1.z; a0.w += a1.w;
            a0.x += __shfl_xor_sync(0xffffffffu, a0.x, 16);
            a0.y += __shfl_xor_sync(0xffffffffu, a0.y, 16);
            a0.z += __shfl_xor_sync(0xffffffffu, a0.z, 16);
            a0.w += __shfl_xor_sync(0xffffffffu, a0.w, 16);
            a0.x = fmaxf(a0.x + bq.x, 0.f);
            a0.y = fmaxf(a0.y + bq.y, 0.f);
            a0.z = fmaxf(a0.z + bq.z, 0.f);
            a0.w = fmaxf(a0.w + bq.w, 0.f);
        }

        if (half == 0) {
            // transposed swizzled store: k = q*4+j, s(k) = (k>>2)<<1 = 2q
            const int col = nl ^ (q * 2);
            xs[(q * 4 + 0) * 128 + col] = a0.x;
            xs[(q * 4 + 1) * 128 + col] = a0.y;
            xs[(q * 4 + 2) * 128 + col] = a0.z;
            xs[(q * 4 + 3) * 128 + col] = a0.w;
        }
    }
    __syncthreads();

    // ---- phase 2: GEMM (K=64) ----
    const int tx = t & 15;
    const int ty = t >> 4;
    const int c0 = tx * 4;

    unsigned long long acc[4][4];
    #pragma unroll
    for (int j = 0; j < 4; j++)
        #pragma unroll
        for (int c = 0; c < 4; c++) acc[j][c] = 0ULL;

    for (int k4 = 0; k4 < 64; k4 += 4) {
        const int s = ((k4 >> 2) & 15) << 1;
        int r0 = (ty * 8 + 0) ^ s;
        int r1 = (ty * 8 + 2) ^ s;
        int r2 = (ty * 8 + 4) ^ s;
        int r3 = (ty * 8 + 6) ^ s;
        #pragma unroll
        for (int kk = 0; kk < 4; kk++) {
            const int k = k4 + kk;
            float4 w4 = *(const float4*)(ws + k * 64 + c0);
            unsigned long long wd0, wd1, wd2, wd3;
            PACK2(wd0, __float_as_uint(w4.x), __float_as_uint(w4.x));
            PACK2(wd1, __float_as_uint(w4.y), __float_as_uint(w4.y));
            PACK2(wd2, __float_as_uint(w4.z), __float_as_uint(w4.z));
            PACK2(wd3, __float_as_uint(w4.w), __float_as_uint(w4.w));
            const float* xr = xs + k * 128;
            unsigned long long x0 = *(const unsigned long long*)(xr + r0);
            unsigned long long x1 = *(const unsigned long long*)(xr + r1);
            unsigned long long x2 = *(const unsigned long long*)(xr + r2);
            unsigned long long x3 = *(const unsigned long long*)(xr + r3);
            FMA_F32X2(acc[0][0], x0, wd0, acc[0][0]);
            FMA_F32X2(acc[0][1], x0, wd1, acc[0][1]);
            FMA_F32X2(acc[0][2], x0, wd2, acc[0][2]);
            FMA_F32X2(acc[0][3], x0, wd3, acc[0][3]);
            FMA_F32X2(acc[1][0], x1, wd0, acc[1][0]);
            FMA_F32X2(acc[1][1], x1, wd1, acc[1][1]);
            FMA_F32X2(acc[1][2], x1, wd2, acc[1][2]);
            FMA_F32X2(acc[1][3], x1, wd3, acc[1][3]);
            FMA_F32X2(acc[2][0], x2, wd0, acc[2][0]);
            FMA_F32X2(acc[2][1], x2, wd1, acc[2][1]);
            FMA_F32X2(acc[2][2], x2, wd2, acc[2][2]);
            FMA_F32X2(acc[2][3], x2, wd3, acc[2][3]);
            FMA_F32X2(acc[3][0], x3, wd0, acc[3][0]);
            FMA_F32X2(acc[3][1], x3, wd1, acc[3][1]);
            FMA_F32X2(acc[3][2], x3, wd2, acc[3][2]);
            FMA_F32X2(acc[3][3], x3, wd3, acc[3][3]);
        }
    }

    #pragma unroll
    for (int j = 0; j < 4; j++) {
        unsigned int lo0, hi0, lo1, hi1, lo2, hi2, lo3, hi3;
        UNPACK2(lo0, hi0, acc[j][0]);
        UNPACK2(lo1, hi1, acc[j][1]);
        UNPACK2(lo2, hi2, acc[j][2]);
        UNPACK2(lo3, hi3, acc[j][3]);
        int n0 = base + ty * 8 + 2 * j;
        if (n0 < n) {
            *(float4*)(hw_out + (size_t)n0 * 64 + c0) =
                make_float4(__uint_as_float(lo0), __uint_as_float(lo1),
                            __uint_as_float(lo2), __uint_as_float(lo3));
        }
        if (n0 + 1 < n) {
            *(float4*)(hw_out + (size_t)(n0 + 1) * 64 + c0) =
                make_float4(__uint_as_float(hi0), __uint_as_float(hi1),
                            __uint_as_float(hi2), __uint_as_float(hi3));
        }
    }
}

// ---------------- standalone aggregation (layer 3, writes output) ----------

__global__ void __launch_bounds__(256) agg64(
        const float* __restrict__ hw, const float* __restrict__ bias,
        float* __restrict__ out, int n, int doRelu) {
    int warp = (blockIdx.x * blockDim.x + threadIdx.x) >> 5;
    if (warp >= n) return;
    const int lane = threadIdx.x & 31;
    const int half = lane >> 4;
    const int q    = lane & 15;

    const int beg = g_off[warp];
    const int end = g_off[warp + 1];

    float4 a0 = make_float4(0.f, 0.f, 0.f, 0.f);
    float4 a1 = make_float4(0.f, 0.f, 0.f, 0.f);
    int e = beg;
    for (; e + 3 < end; e += 4) {
        int s0 = g_csr[e + half];
        int s1 = g_csr[e + 2 + half];
        float4 v0 = ((const float4*)(hw + (size_t)s0 * 64))[q];
        float4 v1 = ((const float4*)(hw + (size_t)s1 * 64))[q];
        a0.x += v0.x; a0.y += v0.y; a0.z += v0.z; a0.w += v0.w;
        a1.x += v1.x; a1.y += v1.y; a1.z += v1.z; a1.w += v1.w;
    }
    for (; e + 1 < end; e += 2) {
        int s0 = g_csr[e + half];
        float4 v0 = ((const float4*)(hw + (size_t)s0 * 64))[q];
        a0.x += v0.x; a0.y += v0.y; a0.z += v0.z; a0.w += v0.w;
    }
    if (e < end && half == 0) {
        int s0 = g_csr[e];
        float4 v0 = ((const float4*)(hw + (size_t)s0 * 64))[q];
        a0.x += v0.x; a0.y += v0.y; a0.z += v0.z; a0.w += v0.w;
    }

    a0.x += a1.x; a0.y += a1.y; a0.z += a1.z; a0.w += a1.w;

    a0.x += __shfl_xor_sync(0xffffffffu, a0.x, 16);
    a0.y += __shfl_xor_sync(0xffffffffu, a0.y, 16);
    a0.z += __shfl_xor_sync(0xffffffffu, a0.z, 16);
    a0.w += __shfl_xor_sync(0xffffffffu, a0.w, 16);

    if (half == 0) {
        float4 b = ((const float4*)bias)[q];
        a0.x += b.x; a0.y += b.y; a0.z += b.z; a0.w += b.w;
        if (doRelu) {
            a0.x = fmaxf(a0.x, 0.f); a0.y = fmaxf(a0.y, 0.f);
            a0.z = fmaxf(a0.z, 0.f); a0.w = fmaxf(a0.w, 0.f);
        }
        ((float4*)(out + (size_t)warp * 64))[q] = a0;
    }
}

// ---------------- streams/events for CSR||GEMM1 overlap ----------------

static cudaStream_t g_s2;
static cudaEvent_t  g_ev_fork, g_ev_join;
static struct HxInit {
    HxInit() {
        cudaStreamCreateWithFlags(&g_s2, cudaStreamNonBlocking);
        cudaEventCreateWithFlags(&g_ev_fork, cudaEventDisableTiming);
        cudaEventCreateWithFlags(&g_ev_join, cudaEventDisableTiming);
    }
} g_hx_init;

// ---------------- launch ----------------

extern "C" void kernel_launch(void* const* d_in, const int* in_sizes, int n_in,
                              void* d_out, int out_size) {
    const float* x    = (const float*)d_in[0];
    const int*   esrc = (const int*)  d_in[1];
    const int*   edst = (const int*)  d_in[2];
    const float* W1   = (const float*)d_in[3];
    const float* b1   = (const float*)d_in[4];
    const float* W2   = (const float*)d_in[5];
    const float* b2   = (const float*)d_in[6];
    const float* W3   = (const float*)d_in[7];
    const float* b3   = (const float*)d_in[8];
    float* out = (float*)d_out;

    const int N = in_sizes[0] / 128;
    const int E = in_sizes[1];

    float *hw = nullptr, *h = nullptr;
    cudaGetSymbolAddress((void**)&hw, g_hw);
    cudaGetSymbolAddress((void**)&h,  g_h);

    const int smem1 = (128 * 128 + 128 * 64) * 4;   // K=128: 98304 B
    const int smemF = (64 * 128  + 64 * 64)  * 4;   // fused: 49152 B
    cudaFuncSetAttribute(gemm64<128>,   cudaFuncAttributeMaxDynamicSharedMemorySize, smem1);
    cudaFuncSetAttribute(fused_agg_gemm, cudaFuncAttributeMaxDynamicSharedMemorySize, smemF);

    const int gblocks = (N + 127) / 128;
    const int ablocks = (N + 7) / 8;
    const int ntot    = N + 1;
    const int nb      = (ntot + 1023) / 1024;

    // Fork: CSR build on g_s2, concurrent with layer-1 GEMM on main stream.
    cudaEventRecord(g_ev_fork, 0);
    cudaStreamWaitEvent(g_s2, g_ev_fork, 0);

    zero_deg   <<<(N + 255) / 256, 256, 0, g_s2>>>(N);
    hist_kernel<<<(E + 255) / 256, 256, 0, g_s2>>>(edst, E);
    scan_block <<<nb, 1024, 0, g_s2>>>(ntot);
    scan_sums  <<<1, 128, 0, g_s2>>>(nb);
    scan_add   <<<nb, 1024, 0, g_s2>>>(ntot);
    fill_csr   <<<(E + 255) / 256, 256, 0, g_s2>>>(esrc, edst, E);
    cudaEventRecord(g_ev_join, g_s2);

    gemm64<128><<<gblocks, 256, smem1>>>(x, W1, hw, N);   // hw1 = x @ W1

    cudaStreamWaitEvent(0, g_ev_join, 0);

    // hw2 = relu(agg(hw1)+b1) @ W2 ; hw3 = relu(agg(hw2)+b2) @ W3
    fused_agg_gemm<<<gblocks, 256, smemF>>>(hw, b1, W2, h,  N);
    fused_agg_gemm<<<gblocks, 256, smemF>>>(h,  b2, W3, hw, N);

    // out = agg(hw3) + b3
    agg64<<<ablocks, 256>>>(hw, b3, out, N, 0);
}

// round 16
// speedup vs baseline: 1.0964x; 1.0964x over previous
#include <cuda_runtime.h>
#include <cstdint>

// ---------------------------------------------------------------------------
// GCN (3-layer, sum-aggregate) on GB300.
// R14: fixes R13's read-write race. R13 overlapped AGG(k) chunk1 (which
// GATHERS ARBITRARY rows of its input buffer) with GEMM(k+1) chunk0 writing
// that same buffer. Now triple-buffered: each overlapped AGG/GEMM pair reads
// and writes DISJOINT buffers:
//   G1: x->hwA ; A1: hwA->h ; G2: h->hwB   (A1c1 reads hwA, G2c0 writes hwB)
//   A2: hwB->h ; G3: h->hwA                (A2c1 reads hwB, G3c0 writes hwA)
//   A3: hwA->out.
// Kernels byte-identical to the 225.7us R9 set (+range params).
// ---------------------------------------------------------------------------

#define MAX_N 100000
#define MAX_E 1600000

__device__ int   g_deg[MAX_N];
__device__ int   g_off[MAX_N + 1];
__device__ int   g_cur[MAX_N];
__device__ int   g_csr[MAX_E];
__device__ int   g_bsums[256];
__device__ float g_hwA[(size_t)MAX_N * 64];
__device__ float g_hwB[(size_t)MAX_N * 64];
__device__ float g_h  [(size_t)MAX_N * 64];

// packed fp32 helpers (Blackwell f32x2 pipe)
#define FMA_F32X2(d, a, b, c) \
    asm("fma.rn.f32x2 %0, %1, %2, %3;" : "=l"(d) : "l"(a), "l"(b), "l"(c))
#define PACK2(out, lo, hi) \
    asm("mov.b64 %0, {%1, %2};" : "=l"(out) : "r"(lo), "r"(hi))
#define UNPACK2(lo, hi, in) \
    asm("mov.b64 {%0, %1}, %2;" : "=r"(lo), "=r"(hi) : "l"(in))

// ---------------- CSR build ----------------

__global__ void zero_deg(int n) {
    int i = blockIdx.x * blockDim.x + threadIdx.x;
    if (i < n) g_deg[i] = 0;
}

__global__ void hist_kernel(const int* __restrict__ dst, int e) {
    int i = blockIdx.x * blockDim.x + threadIdx.x;
    if (i < e) atomicAdd(&g_deg[dst[i]], 1);
}

__global__ void __launch_bounds__(1024) scan_block(int n_total) {
    __shared__ int wsum[32];
    int gid  = blockIdx.x * 1024 + threadIdx.x;
    int lane = threadIdx.x & 31;
    int wid  = threadIdx.x >> 5;
    int v = (gid < n_total - 1) ? g_deg[gid] : 0;

    int inc = v;
    #pragma unroll
    for (int d = 1; d < 32; d <<= 1) {
        int t = __shfl_up_sync(0xffffffffu, inc, d);
        if (lane >= d) inc += t;
    }
    if (lane == 31) wsum[wid] = inc;
    __syncthreads();
    if (wid == 0) {
        int s = wsum[lane];
        #pragma unroll
        for (int d = 1; d < 32; d <<= 1) {
            int t = __shfl_up_sync(0xffffffffu, s, d);
            if (lane >= d) s += t;
        }
        wsum[lane] = s;
    }
    __syncthreads();
    int add = wid ? wsum[wid - 1] : 0;
    if (gid < n_total) g_off[gid] = inc - v + add;
    if (threadIdx.x == 1023) g_bsums[blockIdx.x] = inc + add;
}

__global__ void scan_sums(int nb) {
    __shared__ int ws[4];
    const int t    = threadIdx.x;
    const int lane = t & 31;
    const int w    = t >> 5;
    int v = (t < nb) ? g_bsums[t] : 0;
    int inc = v;
    #pragma unroll
    for (int d = 1; d < 32; d <<= 1) {
        int s = __shfl_up_sync(0xffffffffu, inc, d);
        if (lane >= d) inc += s;
    }
    if (lane == 31) ws[w] = inc;
    __syncthreads();
    int add = 0;
    #pragma unroll
    for (int i = 0; i < 4; i++) add += (i < w) ? ws[i] : 0;
    if (t < nb) g_bsums[t] = inc - v + add;
}

__global__ void __launch_bounds__(1024) scan_add(int n_total) {
    int gid = blockIdx.x * 1024 + threadIdx.x;
    if (gid < n_total) {
        int v = g_off[gid] + g_bsums[blockIdx.x];
        g_off[gid] = v;
        if (gid < n_total - 1) g_cur[gid] = v;
    }
}

__global__ void fill_csr(const int* __restrict__ src, const int* __restrict__ dst, int e) {
    int i = blockIdx.x * blockDim.x + threadIdx.x;
    if (i < e) {
        int p = atomicAdd(&g_cur[dst[i]], 1);
        g_csr[p] = src[i];
    }
}

// ---------------- dense GEMM: Y[n,64] = X[n,K] @ W[K,64] ----------------
// FFMA2 path, transposed + XOR-swizzled X tile (proven in R9).
// base0: first node of this chunk (multiple of 128).

template <int K>
__global__ void __launch_bounds__(256) gemm64(const float* __restrict__ X,
                                              const float* __restrict__ W,
                                              float* __restrict__ Y, int n,
                                              int base0) {
    extern __shared__ float smem[];
    float* xs = smem;                 // [K][128] swizzled, transposed
    float* ws = smem + K * 128;       // [K][64]
    const int t    = threadIdx.x;
    const int base = base0 + blockIdx.x * 128;

    for (int i = t; i < K * 16; i += 256)
        ((float4*)ws)[i] = ((const float4*)W)[i];

    for (int i = t; i < 128 * (K / 4); i += 256) {
        int r  = i / (K / 4);
        int c4 = i % (K / 4);
        int node = base + r;
        float4 v = make_float4(0.f, 0.f, 0.f, 0.f);
        if (node < n) v = ((const float4*)(X + (size_t)node * K))[c4];
        int s  = (c4 & 15) << 1;
        int rs = r ^ s;
        xs[(c4 * 4 + 0) * 128 + rs] = v.x;
        xs[(c4 * 4 + 1) * 128 + rs] = v.y;
        xs[(c4 * 4 + 2) * 128 + rs] = v.z;
        xs[(c4 * 4 + 3) * 128 + rs] = v.w;
    }
    __syncthreads();

    const int tx = t & 15;
    const int ty = t >> 4;
    const int c0 = tx * 4;

    unsigned long long acc[4][4];
    #pragma unroll
    for (int j = 0; j < 4; j++)
        #pragma unroll
        for (int c = 0; c < 4; c++) acc[j][c] = 0ULL;

    for (int k4 = 0; k4 < K; k4 += 4) {
        const int s = ((k4 >> 2) & 15) << 1;
        int r0 = (ty * 8 + 0) ^ s;
        int r1 = (ty * 8 + 2) ^ s;
        int r2 = (ty * 8 + 4) ^ s;
        int r3 = (ty * 8 + 6) ^ s;
        #pragma unroll
        for (int kk = 0; kk < 4; kk++) {
            const int k = k4 + kk;
            float4 w4 = *(const float4*)(ws + k * 64 + c0);
            unsigned long long wd0, wd1, wd2, wd3;
            PACK2(wd0, __float_as_uint(w4.x), __float_as_uint(w4.x));
            PACK2(wd1, __float_as_uint(w4.y), __float_as_uint(w4.y));
            PACK2(wd2, __float_as_uint(w4.z), __float_as_uint(w4.z));
            PACK2(wd3, __float_as_uint(w4.w), __float_as_uint(w4.w));
            const float* xr = xs + k * 128;
            unsigned long long x0 = *(const unsigned long long*)(xr + r0);
            unsigned long long x1 = *(const unsigned long long*)(xr + r1);
            unsigned long long x2 = *(const unsigned long long*)(xr + r2);
            unsigned long long x3 = *(const unsigned long long*)(xr + r3);
            FMA_F32X2(acc[0][0], x0, wd0, acc[0][0]);
            FMA_F32X2(acc[0][1], x0, wd1, acc[0][1]);
            FMA_F32X2(acc[0][2], x0, wd2, acc[0][2]);
            FMA_F32X2(acc[0][3], x0, wd3, acc[0][3]);
            FMA_F32X2(acc[1][0], x1, wd0, acc[1][0]);
            FMA_F32X2(acc[1][1], x1, wd1, acc[1][1]);
            FMA_F32X2(acc[1][2], x1, wd2, acc[1][2]);
            FMA_F32X2(acc[1][3], x1, wd3, acc[1][3]);
            FMA_F32X2(acc[2][0], x2, wd0, acc[2][0]);
            FMA_F32X2(acc[2][1], x2, wd1, acc[2][1]);
            FMA_F32X2(acc[2][2], x2, wd2, acc[2][2]);
            FMA_F32X2(acc[2][3], x2, wd3, acc[2][3]);
            FMA_F32X2(acc[3][0], x3, wd0, acc[3][0]);
            FMA_F32X2(acc[3][1], x3, wd1, acc[3][1]);
            FMA_F32X2(acc[3][2], x3, wd2, acc[3][2]);
            FMA_F32X2(acc[3][3], x3, wd3, acc[3][3]);
        }
    }

    #pragma unroll
    for (int j = 0; j < 4; j++) {
        unsigned int lo0, hi0, lo1, hi1, lo2, hi2, lo3, hi3;
        UNPACK2(lo0, hi0, acc[j][0]);
        UNPACK2(lo1, hi1, acc[j][1]);
        UNPACK2(lo2, hi2, acc[j][2]);
        UNPACK2(lo3, hi3, acc[j][3]);
        int n0 = base + ty * 8 + 2 * j;
        if (n0 < n) {
            *(float4*)(Y + (size_t)n0 * 64 + c0) =
                make_float4(__uint_as_float(lo0), __uint_as_float(lo1),
                            __uint_as_float(lo2), __uint_as_float(lo3));
        }
        if (n0 + 1 < n) {
            *(float4*)(Y + (size_t)(n0 + 1) * 64 + c0) =
                make_float4(__uint_as_float(hi0), __uint_as_float(hi1),
                            __uint_as_float(hi2), __uint_as_float(hi3));
        }
    }
}

// ---------------- aggregation (warp per node, [n0, n1) range) --------------

__global__ void __launch_bounds__(256) agg64(
        const float* __restrict__ hw, const float* __restrict__ bias,
        float* __restrict__ out, int n0, int n1, int doRelu) {
    int warp = n0 + ((blockIdx.x * blockDim.x + threadIdx.x) >> 5);
    if (warp >= n1) return;
    const int lane = threadIdx.x & 31;
    const int half = lane >> 4;
    const int q    = lane & 15;

    const int beg = g_off[warp];
    const int end = g_off[warp + 1];

    float4 a0 = make_float4(0.f, 0.f, 0.f, 0.f);
    float4 a1 = make_float4(0.f, 0.f, 0.f, 0.f);
    int e = beg;
    for (; e + 3 < end; e += 4) {
        int s0 = g_csr[e + half];
        int s1 = g_csr[e + 2 + half];
        float4 v0 = ((const float4*)(hw + (size_t)s0 * 64))[q];
        float4 v1 = ((const float4*)(hw + (size_t)s1 * 64))[q];
        a0.x += v0.x; a0.y += v0.y; a0.z += v0.z; a0.w += v0.w;
        a1.x += v1.x; a1.y += v1.y; a1.z += v1.z; a1.w += v1.w;
    }
    for (; e + 1 < end; e += 2) {
        int s0 = g_csr[e + half];
        float4 v0 = ((const float4*)(hw + (size_t)s0 * 64))[q];
        a0.x += v0.x; a0.y += v0.y; a0.z += v0.z; a0.w += v0.w;
    }
    if (e < end && half == 0) {
        int s0 = g_csr[e];
        float4 v0 = ((const float4*)(hw + (size_t)s0 * 64))[q];
        a0.x += v0.x; a0.y += v0.y; a0.z += v0.z; a0.w += v0.w;
    }

    a0.x += a1.x; a0.y += a1.y; a0.z += a1.z; a0.w += a1.w;

    a0.x += __shfl_xor_sync(0xffffffffu, a0.x, 16);
    a0.y += __shfl_xor_sync(0xffffffffu, a0.y, 16);
    a0.z += __shfl_xor_sync(0xffffffffu, a0.z, 16);
    a0.w += __shfl_xor_sync(0xffffffffu, a0.w, 16);

    if (half == 0) {
        float4 b = ((const float4*)bias)[q];
        a0.x += b.x; a0.y += b.y; a0.z += b.z; a0.w += b.w;
        if (doRelu) {
            a0.x = fmaxf(a0.x, 0.f); a0.y = fmaxf(a0.y, 0.f);
            a0.z = fmaxf(a0.z, 0.f); a0.w = fmaxf(a0.w, 0.f);
        }
        ((float4*)(out + (size_t)warp * 64))[q] = a0;
    }
}

// ---------------- streams/events ----------------
// Created once at static init (no device-mem allocs in kernel_launch).

static cudaStream_t g_s2;
static cudaEvent_t  g_ev_fork, g_ev_join;
static cudaEvent_t  g_ev_a1c0, g_ev_a1c1, g_ev_g2;
static cudaEvent_t  g_ev_a2c0, g_ev_a2c1, g_ev_g3;
static struct HxInit {
    HxInit() {
        cudaStreamCreateWithFlags(&g_s2, cudaStreamNonBlocking);
        cudaEventCreateWithFlags(&g_ev_fork, cudaEventDisableTiming);
        cudaEventCreateWithFlags(&g_ev_join, cudaEventDisableTiming);
        cudaEventCreateWithFlags(&g_ev_a1c0, cudaEventDisableTiming);
        cudaEventCreateWithFlags(&g_ev_a1c1, cudaEventDisableTiming);
        cudaEventCreateWithFlags(&g_ev_g2,   cudaEventDisableTiming);
        cudaEventCreateWithFlags(&g_ev_a2c0, cudaEventDisableTiming);
        cudaEventCreateWithFlags(&g_ev_a2c1, cudaEventDisableTiming);
        cudaEventCreateWithFlags(&g_ev_g3,   cudaEventDisableTiming);
    }
} g_hx_init;

// ---------------- launch ----------------

extern "C" void kernel_launch(void* const* d_in, const int* in_sizes, int n_in,
                              void* d_out, int out_size) {
    const float* x    = (const float*)d_in[0];
    const int*   esrc = (const int*)  d_in[1];
    const int*   edst = (const int*)  d_in[2];
    const float* W1   = (const float*)d_in[3];
    const float* b1   = (const float*)d_in[4];
    const float* W2   = (const float*)d_in[5];
    const float* b2   = (const float*)d_in[6];
    const float* W3   = (const float*)d_in[7];
    const float* b3   = (const float*)d_in[8];
    float* out = (float*)d_out;

    const int N = in_sizes[0] / 128;
    const int E = in_sizes[1];

    float *hwA = nullptr, *hwB = nullptr, *h = nullptr;
    cudaGetSymbolAddress((void**)&hwA, g_hwA);
    cudaGetSymbolAddress((void**)&hwB, g_hwB);
    cudaGetSymbolAddress((void**)&h,   g_h);

    const int smem1 = (128 * 128 + 128 * 64) * 4;   // K=128: 98304 B
    const int smem2 = (64 * 128  + 64 * 64)  * 4;   // K=64 : 49152 B
    cudaFuncSetAttribute(gemm64<128>, cudaFuncAttributeMaxDynamicSharedMemorySize, smem1);
    cudaFuncSetAttribute(gemm64<64>,  cudaFuncAttributeMaxDynamicSharedMemorySize, smem2);

    const int ntot = N + 1;
    const int nb   = (ntot + 1023) / 1024;

    // chunk split at a 128-multiple near N/2
    const int cut = ((N / 2 + 127) / 128) * 128;
    const int gb0 = cut / 128;                    // gemm blocks chunk0
    const int gb1 = (N - cut + 127) / 128;        // gemm blocks chunk1
    const int ab0 = (cut + 7) / 8;                // agg blocks chunk0
    const int ab1 = (N - cut + 7) / 8;            // agg blocks chunk1
    const int abF = (N + 7) / 8;                  // agg blocks full
    const int gbF = (N + 127) / 128;              // gemm blocks full

    // --- fork: CSR build on g_s2, concurrent with layer-1 GEMM ---
    cudaEventRecord(g_ev_fork, 0);
    cudaStreamWaitEvent(g_s2, g_ev_fork, 0);

    zero_deg   <<<(N + 255) / 256, 256, 0, g_s2>>>(N);
    hist_kernel<<<(E + 255) / 256, 256, 0, g_s2>>>(edst, E);
    scan_block <<<nb, 1024, 0, g_s2>>>(ntot);
    scan_sums  <<<1, 128, 0, g_s2>>>(nb);
    scan_add   <<<nb, 1024, 0, g_s2>>>(ntot);
    fill_csr   <<<(E + 255) / 256, 256, 0, g_s2>>>(esrc, edst, E);
    cudaEventRecord(g_ev_join, g_s2);

    gemm64<128><<<gbF, 256, smem1>>>(x, W1, hwA, N, 0);   // hwA = x @ W1

    cudaStreamWaitEvent(0, g_ev_join, 0);

    // --- layer 1 agg (reads hwA) + layer 2 gemm (writes hwB): disjoint ---
    agg64<<<ab0, 256>>>(hwA, b1, h, 0,   cut, 1);
    cudaEventRecord(g_ev_a1c0, 0);
    agg64<<<ab1, 256>>>(hwA, b1, h, cut, N,   1);
    cudaEventRecord(g_ev_a1c1, 0);

    cudaStreamWaitEvent(g_s2, g_ev_a1c0, 0);
    gemm64<64><<<gb0, 256, smem2, g_s2>>>(h, W2, hwB, N, 0);    // overlaps A1c1
    cudaStreamWaitEvent(g_s2, g_ev_a1c1, 0);
    gemm64<64><<<gb1, 256, smem2, g_s2>>>(h, W2, hwB, N, cut);
    cudaEventRecord(g_ev_g2, g_s2);

    cudaStreamWaitEvent(0, g_ev_g2, 0);   // A2 gathers arbitrary rows of hwB

    // --- layer 2 agg (reads hwB) + layer 3 gemm (writes hwA): disjoint ---
    agg64<<<ab0, 256>>>(hwB, b2, h, 0,   cut, 1);
    cudaEventRecord(g_ev_a2c0, 0);
    agg64<<<ab1, 256>>>(hwB, b2, h, cut, N,   1);
    cudaEventRecord(g_ev_a2c1, 0);

    cudaStreamWaitEvent(g_s2, g_ev_a2c0, 0);
    gemm64<64><<<gb0, 256, smem2, g_s2>>>(h, W3, hwA, N, 0);    // overlaps A2c1
    cudaStreamWaitEvent(g_s2, g_ev_a2c1, 0);
    gemm64<64><<<gb1, 256, smem2, g_s2>>>(h, W3, hwA, N, cut);
    cudaEventRecord(g_ev_g3, g_s2);

    cudaStreamWaitEvent(0, g_ev_g3, 0);

    // --- final aggregation -> out ---
    agg64<<<abF, 256>>>(hwA, b3, out, 0, N, 0);
}